// round 14
// baseline (speedup 1.0000x reference)
#include <cuda_runtime.h>
#include <cuda_fp16.h>
#include <stdint.h>
#include <math.h>

#define BB 64
#define LL 196
#define DD 2048
#define II 512
#define MM (BB * LL)   // 12544

typedef __half f16;

// ---------------- device scratch (allocation-free) ----------------
__device__ f16 g_fv_h[(size_t)MM * DD];
__device__ f16 g_fvs_h[(size_t)MM * II];
__device__ f16 g_WfT_h[(size_t)II * DD];   // [I, D] K-major
__device__ f16 g_WaT_h[(size_t)DD * II];   // [D, I] K-major
__device__ float g_hs[BB * II];

// ---------------- helpers ----------------
__device__ __forceinline__ uint32_t smem_u32(const void* p) {
    uint32_t a;
    asm("{ .reg .u64 t; cvta.to.shared.u64 t, %1; cvt.u32.u64 %0, t; }"
        : "=r"(a) : "l"(p));
    return a;
}
__device__ __forceinline__ void cp_async16(uint32_t s, const void* g) {
    asm volatile("cp.async.cg.shared.global [%0], [%1], 16;" :: "r"(s), "l"(g));
}
__device__ __forceinline__ void cp_commit() {
    asm volatile("cp.async.commit_group;" ::: "memory");
}
__device__ __forceinline__ void cp_wait1() {
    asm volatile("cp.async.wait_group 1;" ::: "memory");
}
__device__ __forceinline__ void cp_wait0() {
    asm volatile("cp.async.wait_group 0;" ::: "memory");
}
__device__ __forceinline__ void ldsm4(uint32_t& r0, uint32_t& r1, uint32_t& r2,
                                      uint32_t& r3, uint32_t addr) {
    asm volatile("ldmatrix.sync.aligned.m8n8.x4.shared.b16 {%0,%1,%2,%3}, [%4];"
                 : "=r"(r0), "=r"(r1), "=r"(r2), "=r"(r3) : "r"(addr));
}
__device__ __forceinline__ void mma16816(float* c, const uint32_t* a,
                                         const uint32_t* b) {
    asm volatile(
        "mma.sync.aligned.m16n8k16.row.col.f32.f16.f16.f32 "
        "{%0,%1,%2,%3}, {%4,%5,%6,%7}, {%8,%9}, {%0,%1,%2,%3};"
        : "+f"(c[0]), "+f"(c[1]), "+f"(c[2]), "+f"(c[3])
        : "r"(a[0]), "r"(a[1]), "r"(a[2]), "r"(a[3]), "r"(b[0]), "r"(b[1]));
}

// ---------------- fused prep kernel ----------------
// blocks [0,1024): transpose Wf [2048,512] -> WfT [512,2048]
// blocks [1024,2048): transpose Wa [512,2048] -> WaT [2048,512]
// blocks [2048,2176): hs = hidden @ Wh + bh
// blocks [2176,...): fv -> fp16
__device__ __forceinline__ void transpose_body(const float* __restrict__ in,
                                               f16* __restrict__ oh,
                                               int K, int N, int bx, int by,
                                               int tid, float (*t)[33]) {
    int n0 = bx * 32, k0 = by * 32;
    int tx = tid & 31, ty = tid >> 5;   // (32, 8)
#pragma unroll
    for (int i = 0; i < 32; i += 8)
        t[ty + i][tx] = in[(size_t)(k0 + ty + i) * N + n0 + tx];
    __syncthreads();
#pragma unroll
    for (int i = 0; i < 32; i += 8)
        oh[(size_t)(n0 + ty + i) * K + k0 + tx] = __float2half_rn(t[tx][ty + i]);
}

__global__ __launch_bounds__(256)
void prep_kernel(const float* __restrict__ fv, const float* __restrict__ hidden,
                 const float* __restrict__ Wh, const float* __restrict__ bh,
                 const float* __restrict__ Wf, const float* __restrict__ Wa) {
    __shared__ float t[32][33];
    int blk = blockIdx.x, tid = threadIdx.x;
    if (blk < 1024) {
        transpose_body(Wf, g_WfT_h, DD, II, blk & 15, blk >> 4, tid, t);
    } else if (blk < 2048) {
        int bb = blk - 1024;
        transpose_body(Wa, g_WaT_h, II, DD, bb & 63, bb >> 6, tid, t);
    } else if (blk < 2176) {
        int idx = (blk - 2048) * 256 + tid;   // 0..BB*II
        int b = idx >> 9, i = idx & 511;
        const float* h = hidden + b * II;
        float acc = bh[i];
#pragma unroll 4
        for (int j = 0; j < II; ++j)
            acc = fmaf(h[j], Wh[j * II + i], acc);
        g_hs[idx] = acc;
    } else {
        size_t i = (size_t)(blk - 2176) * 256 + tid;   // over MM*DD/4
        float4 v = ((const float4*)fv)[i];
        ((__half2*)g_fv_h)[2 * i]     = __floats2half2_rn(v.x, v.y);
        ((__half2*)g_fv_h)[2 * i + 1] = __floats2half2_rn(v.z, v.w);
    }
}
#define PREP_BLOCKS (2176 + (MM * DD / 4) / 256)

// ---------------- tensor-core (mma.sync) GEMM ----------------
// C = A@B^T; A [M,K0] fp16 row-major, B [N,K0] fp16 K-major. Single pass.
// Tile 128x128, BK=64, 8 warps (64x32), 2-stage cp.async double buffer.
// Smem row: 128B (64 f16), swizzle byteoff = row*128 + (cb ^ ((row&7)<<4)).

__device__ __forceinline__ void load_tile_async(uint32_t dst, const f16* src,
                                                int ldk, int tid) {
#pragma unroll
    for (int i = 0; i < 4; ++i) {
        int chunk = i * 256 + tid;
        int r = chunk >> 3, c16 = chunk & 7;
        const char* g = (const char*)src + (size_t)r * ldk * 2 + c16 * 16;
        uint32_t s = dst + r * 128 + ((c16 * 16) ^ ((r & 7) << 4));
        cp_async16(s, g);
    }
}

template <int EPI>
__global__ __launch_bounds__(256, 2)
void mma_gemm(const f16* __restrict__ Ah, const f16* __restrict__ Bh,
              const float* __restrict__ bias,
              float* __restrict__ Cf, f16* __restrict__ Ch,
              int N, int K0) {
    extern __shared__ char smem[];
    uint32_t sbase = smem_u32(smem);
    int tid = threadIdx.x, lane = tid & 31, wid = tid >> 5;
    int warp_m = wid >> 2, warp_n = wid & 3;
    int row0 = blockIdx.y * 128, col0 = blockIdx.x * 128;

    float c[4][4][4];
#pragma unroll
    for (int mi = 0; mi < 4; ++mi)
#pragma unroll
        for (int ni = 0; ni < 4; ++ni)
#pragma unroll
            for (int f = 0; f < 4; ++f) c[mi][ni][f] = 0.f;

    int nch = K0 / 64;

    auto issue = [&](int cc) {
        int buf = cc & 1;
        int kk = cc * 64;
        load_tile_async(sbase + buf * 32768, Ah + (size_t)row0 * K0 + kk, K0, tid);
        load_tile_async(sbase + buf * 32768 + 16384, Bh + (size_t)col0 * K0 + kk, K0, tid);
        cp_commit();
    };

    issue(0);

    int la15 = lane & 15, la7 = lane & 7;
    int a_cbsel = (lane >> 4) * 16;
    int b_cbsel = ((lane >> 3) & 1) * 16;
    int b_rowsel = (lane >> 4) * 8;

    for (int cc = 0; cc < nch; ++cc) {
        if (cc + 1 < nch) { issue(cc + 1); cp_wait1(); }
        else              { cp_wait0(); }
        __syncthreads();

        uint32_t sA = sbase + (cc & 1) * 32768;
        uint32_t sB = sA + 16384;
#pragma unroll
        for (int ks = 0; ks < 4; ++ks) {
            uint32_t a[4][4];
#pragma unroll
            for (int mi = 0; mi < 4; ++mi) {
                int row = warp_m * 64 + mi * 16 + la15;
                uint32_t cb = ks * 32 + a_cbsel;
                ldsm4(a[mi][0], a[mi][1], a[mi][2], a[mi][3],
                      sA + row * 128 + (cb ^ ((row & 7) << 4)));
            }
            uint32_t b[4][2];
#pragma unroll
            for (int nb = 0; nb < 2; ++nb) {
                int row = warp_n * 32 + nb * 16 + la7 + b_rowsel;
                uint32_t cb = ks * 32 + b_cbsel;
                ldsm4(b[2 * nb][0], b[2 * nb][1], b[2 * nb + 1][0], b[2 * nb + 1][1],
                      sB + row * 128 + (cb ^ ((row & 7) << 4)));
            }
#pragma unroll
            for (int mi = 0; mi < 4; ++mi)
#pragma unroll
                for (int ni = 0; ni < 4; ++ni)
                    mma16816(c[mi][ni], a[mi], b[ni]);
        }
        __syncthreads();
    }

    // ---------------- epilogue ----------------
    int g = lane >> 2, tg = lane & 3;
#pragma unroll
    for (int mi = 0; mi < 4; ++mi) {
#pragma unroll
        for (int half = 0; half < 2; ++half) {
            int row = row0 + warp_m * 64 + mi * 16 + g + half * 8;
            const float* hsrow = (EPI == 0) ? (g_hs + (size_t)(row / LL) * II) : nullptr;
#pragma unroll
            for (int ni = 0; ni < 4; ++ni) {
                int col = col0 + warp_n * 32 + ni * 8 + tg * 2;
                float v0 = c[mi][ni][2 * half + 0];
                float v1 = c[mi][ni][2 * half + 1];
                v0 += bias[col];
                v1 += bias[col + 1];
                if (EPI == 0) {
                    v0 += hsrow[col];
                    v1 += hsrow[col + 1];
                    *(__half2*)(Ch + (size_t)row * N + col) = __floats2half2_rn(v0, v1);
                } else {
                    *(float2*)(Cf + (size_t)row * N + col) = make_float2(v0, v1);
                }
            }
        }
    }
}

// ---------------- softmax + z: smem-resident e-tile, single global read ----
// CTA = 128 threads handles one (b, 64-column) slab. Pass 1: stream e,
// exp() into smem, partial sums. Pass 2: normalize from smem, write alpha,
// accumulate z from fp16 fv. 4 row-groups x 32 column-pairs per CTA.
#define SMX_SMEM (LL * 64 * 4 + 128 * 8)   // 50176 + 1024 = 51200 B

__global__ __launch_bounds__(128)
void softmax_z_kernel(float* __restrict__ out) {
    extern __shared__ float sm[];               // [LL][64]
    float2* red = (float2*)(sm + LL * 64);      // [128]
    int t = threadIdx.x;
    int b = blockIdx.x >> 5;
    int d0 = (blockIdx.x & 31) * 64;
    int rg = t >> 5;          // row group 0..3 (= warp id)
    int cp = t & 31;          // column pair 0..31
    float* ebase = out + BB * DD + (size_t)b * LL * DD + d0;

    // pass 1: global e -> exp -> smem, partial sums
    float s0 = 0.f, s1 = 0.f;
    for (int l = rg; l < LL; l += 4) {
        float2 v = *(float2*)(ebase + (size_t)l * DD + 2 * cp);
        float e0 = __expf(v.x), e1 = __expf(v.y);
        *(float2*)&sm[l * 64 + 2 * cp] = make_float2(e0, e1);
        s0 += e0;
        s1 += e1;
    }
    red[t] = make_float2(s0, s1);
    __syncthreads();
    float t0 = 0.f, t1 = 0.f;
#pragma unroll
    for (int j = 0; j < 4; ++j) {
        float2 v = red[cp + 32 * j];
        t0 += v.x;
        t1 += v.y;
    }
    float inv0 = 1.f / t0, inv1 = 1.f / t1;

    // pass 2: normalize from smem, write alpha, accumulate z
    const __half2* fbase =
        (const __half2*)g_fv_h + (size_t)b * LL * (DD / 2) + d0 / 2;
    float z0 = 0.f, z1 = 0.f;
    for (int l = rg; l < LL; l += 4) {
        float2 ev = *(float2*)&sm[l * 64 + 2 * cp];
        float p0 = ev.x * inv0, p1 = ev.y * inv1;
        *(float2*)(ebase + (size_t)l * DD + 2 * cp) = make_float2(p0, p1);
        float2 fw = __half22float2(fbase[(size_t)l * (DD / 2) + cp]);
        z0 = fmaf(p0, fw.x, z0);
        z1 = fmaf(p1, fw.y, z1);
    }
    __syncthreads();
    red[t] = make_float2(z0, z1);
    __syncthreads();
    if (t < 32) {
        float a0 = 0.f, a1 = 0.f;
#pragma unroll
        for (int j = 0; j < 4; ++j) {
            float2 v = red[t + 32 * j];
            a0 += v.x;
            a1 += v.y;
        }
        ((float2*)(out + (size_t)b * DD + d0))[t] = make_float2(a0, a1);
    }
}

// ---------------- launch ----------------
#define GEMM_SMEM 65536

extern "C" void kernel_launch(void* const* d_in, const int* in_sizes, int n_in,
                              void* d_out, int out_size) {
    const float* fv     = (const float*)d_in[0];
    const float* hidden = (const float*)d_in[1];
    const float* Wf     = (const float*)d_in[2];
    const float* bf     = (const float*)d_in[3];
    const float* Wh     = (const float*)d_in[4];
    const float* bh     = (const float*)d_in[5];
    const float* Wa     = (const float*)d_in[6];
    const float* ba     = (const float*)d_in[7];
    float* out = (float*)d_out;

    cudaFuncSetAttribute(mma_gemm<0>, cudaFuncAttributeMaxDynamicSharedMemorySize, GEMM_SMEM);
    cudaFuncSetAttribute(mma_gemm<1>, cudaFuncAttributeMaxDynamicSharedMemorySize, GEMM_SMEM);
    cudaFuncSetAttribute(softmax_z_kernel, cudaFuncAttributeMaxDynamicSharedMemorySize, SMX_SMEM);

    void* p;
    cudaGetSymbolAddress(&p, g_fv_h);    f16* fv_h  = (f16*)p;
    cudaGetSymbolAddress(&p, g_fvs_h);   f16* fvs_h = (f16*)p;
    cudaGetSymbolAddress(&p, g_WfT_h);   f16* WfT_h = (f16*)p;
    cudaGetSymbolAddress(&p, g_WaT_h);   f16* WaT_h = (f16*)p;

    // all input conversions in one launch
    prep_kernel<<<PREP_BLOCKS, 256>>>(fv, hidden, Wh, bh, Wf, Wa);

    // gemm1: fvs = fv @ Wf + bf + hs   (M=12544, N=512, K0=2048) -> fp16
    mma_gemm<0><<<dim3(II / 128, MM / 128), 256, GEMM_SMEM>>>(
        fv_h, WfT_h, bf, nullptr, fvs_h, II, DD);

    // gemm2: e = fvs @ Wa + ba   (M=12544, N=2048, K0=512) -> fp32 into out
    float* e = out + BB * DD;
    mma_gemm<1><<<dim3(DD / 128, MM / 128), 256, GEMM_SMEM>>>(
        fvs_h, WaT_h, ba, e, nullptr, DD, II);

    // softmax over L (in place) + z
    softmax_z_kernel<<<BB * DD / 64, 128, SMX_SMEM>>>(out);
}

// round 15
// speedup vs baseline: 1.1909x; 1.1909x over previous
#include <cuda_runtime.h>
#include <cuda_fp16.h>
#include <stdint.h>
#include <math.h>

#define BB 64
#define LL 196
#define DD 2048
#define II 512
#define MM (BB * LL)   // 12544

typedef __half f16;

// ---------------- device scratch (allocation-free) ----------------
__device__ f16 g_fv_h[(size_t)MM * DD];
__device__ f16 g_fvs_h[(size_t)MM * II];
__device__ f16 g_WfT_h[(size_t)II * DD];   // [I, D] K-major
__device__ f16 g_WaT_h[(size_t)DD * II];   // [D, I] K-major
__device__ float g_hs[BB * II];

// ---------------- helpers ----------------
__device__ __forceinline__ uint32_t smem_u32(const void* p) {
    uint32_t a;
    asm("{ .reg .u64 t; cvta.to.shared.u64 t, %1; cvt.u32.u64 %0, t; }"
        : "=r"(a) : "l"(p));
    return a;
}
__device__ __forceinline__ void cp_async16(uint32_t s, const void* g) {
    asm volatile("cp.async.cg.shared.global [%0], [%1], 16;" :: "r"(s), "l"(g));
}
__device__ __forceinline__ void cp_commit() {
    asm volatile("cp.async.commit_group;" ::: "memory");
}
__device__ __forceinline__ void cp_wait1() {
    asm volatile("cp.async.wait_group 1;" ::: "memory");
}
__device__ __forceinline__ void cp_wait0() {
    asm volatile("cp.async.wait_group 0;" ::: "memory");
}
__device__ __forceinline__ void ldsm4(uint32_t& r0, uint32_t& r1, uint32_t& r2,
                                      uint32_t& r3, uint32_t addr) {
    asm volatile("ldmatrix.sync.aligned.m8n8.x4.shared.b16 {%0,%1,%2,%3}, [%4];"
                 : "=r"(r0), "=r"(r1), "=r"(r2), "=r"(r3) : "r"(addr));
}
__device__ __forceinline__ void mma16816(float* c, const uint32_t* a,
                                         const uint32_t* b) {
    asm volatile(
        "mma.sync.aligned.m16n8k16.row.col.f32.f16.f16.f32 "
        "{%0,%1,%2,%3}, {%4,%5,%6,%7}, {%8,%9}, {%0,%1,%2,%3};"
        : "+f"(c[0]), "+f"(c[1]), "+f"(c[2]), "+f"(c[3])
        : "r"(a[0]), "r"(a[1]), "r"(a[2]), "r"(a[3]), "r"(b[0]), "r"(b[1]));
}

// ---------------- fused prep kernel ----------------
// blocks [0,1024): transpose Wf [2048,512] -> WfT [512,2048]
// blocks [1024,2048): transpose Wa [512,2048] -> WaT [2048,512]
// blocks [2048,2176): hs = hidden @ Wh + bh
// blocks [2176,...): fv -> fp16
__device__ __forceinline__ void transpose_body(const float* __restrict__ in,
                                               f16* __restrict__ oh,
                                               int K, int N, int bx, int by,
                                               int tid, float (*t)[33]) {
    int n0 = bx * 32, k0 = by * 32;
    int tx = tid & 31, ty = tid >> 5;   // (32, 8)
#pragma unroll
    for (int i = 0; i < 32; i += 8)
        t[ty + i][tx] = in[(size_t)(k0 + ty + i) * N + n0 + tx];
    __syncthreads();
#pragma unroll
    for (int i = 0; i < 32; i += 8)
        oh[(size_t)(n0 + ty + i) * K + k0 + tx] = __float2half_rn(t[tx][ty + i]);
}

__global__ __launch_bounds__(256)
void prep_kernel(const float* __restrict__ fv, const float* __restrict__ hidden,
                 const float* __restrict__ Wh, const float* __restrict__ bh,
                 const float* __restrict__ Wf, const float* __restrict__ Wa) {
    __shared__ float t[32][33];
    int blk = blockIdx.x, tid = threadIdx.x;
    if (blk < 1024) {
        transpose_body(Wf, g_WfT_h, DD, II, blk & 15, blk >> 4, tid, t);
    } else if (blk < 2048) {
        int bb = blk - 1024;
        transpose_body(Wa, g_WaT_h, II, DD, bb & 63, bb >> 6, tid, t);
    } else if (blk < 2176) {
        int idx = (blk - 2048) * 256 + tid;   // 0..BB*II
        int b = idx >> 9, i = idx & 511;
        const float* h = hidden + b * II;
        float acc = bh[i];
#pragma unroll 4
        for (int j = 0; j < II; ++j)
            acc = fmaf(h[j], Wh[j * II + i], acc);
        g_hs[idx] = acc;
    } else {
        size_t i = (size_t)(blk - 2176) * 256 + tid;   // over MM*DD/4
        float4 v = ((const float4*)fv)[i];
        ((__half2*)g_fv_h)[2 * i]     = __floats2half2_rn(v.x, v.y);
        ((__half2*)g_fv_h)[2 * i + 1] = __floats2half2_rn(v.z, v.w);
    }
}
#define PREP_BLOCKS (2176 + (MM * DD / 4) / 256)

// ---------------- tensor-core (mma.sync) GEMM ----------------
// C = A@B^T; A [M,K0] fp16 row-major, B [N,K0] fp16 K-major. Single pass.
// Tile 128x128, BK=64, 8 warps (64x32), 2-stage cp.async double buffer.
// Smem row: 128B (64 f16), swizzle byteoff = row*128 + (cb ^ ((row&7)<<4)).

__device__ __forceinline__ void load_tile_async(uint32_t dst, const f16* src,
                                                int ldk, int tid) {
#pragma unroll
    for (int i = 0; i < 4; ++i) {
        int chunk = i * 256 + tid;
        int r = chunk >> 3, c16 = chunk & 7;
        const char* g = (const char*)src + (size_t)r * ldk * 2 + c16 * 16;
        uint32_t s = dst + r * 128 + ((c16 * 16) ^ ((r & 7) << 4));
        cp_async16(s, g);
    }
}

template <int EPI>
__global__ __launch_bounds__(256, 2)
void mma_gemm(const f16* __restrict__ Ah, const f16* __restrict__ Bh,
              const float* __restrict__ bias,
              float* __restrict__ Cf, f16* __restrict__ Ch,
              int N, int K0) {
    extern __shared__ char smem[];
    uint32_t sbase = smem_u32(smem);
    int tid = threadIdx.x, lane = tid & 31, wid = tid >> 5;
    int warp_m = wid >> 2, warp_n = wid & 3;
    int row0 = blockIdx.y * 128, col0 = blockIdx.x * 128;

    float c[4][4][4];
#pragma unroll
    for (int mi = 0; mi < 4; ++mi)
#pragma unroll
        for (int ni = 0; ni < 4; ++ni)
#pragma unroll
            for (int f = 0; f < 4; ++f) c[mi][ni][f] = 0.f;

    int nch = K0 / 64;

    auto issue = [&](int cc) {
        int buf = cc & 1;
        int kk = cc * 64;
        load_tile_async(sbase + buf * 32768, Ah + (size_t)row0 * K0 + kk, K0, tid);
        load_tile_async(sbase + buf * 32768 + 16384, Bh + (size_t)col0 * K0 + kk, K0, tid);
        cp_commit();
    };

    issue(0);

    int la15 = lane & 15, la7 = lane & 7;
    int a_cbsel = (lane >> 4) * 16;
    int b_cbsel = ((lane >> 3) & 1) * 16;
    int b_rowsel = (lane >> 4) * 8;

    for (int cc = 0; cc < nch; ++cc) {
        if (cc + 1 < nch) { issue(cc + 1); cp_wait1(); }
        else              { cp_wait0(); }
        __syncthreads();

        uint32_t sA = sbase + (cc & 1) * 32768;
        uint32_t sB = sA + 16384;
#pragma unroll
        for (int ks = 0; ks < 4; ++ks) {
            uint32_t a[4][4];
#pragma unroll
            for (int mi = 0; mi < 4; ++mi) {
                int row = warp_m * 64 + mi * 16 + la15;
                uint32_t cb = ks * 32 + a_cbsel;
                ldsm4(a[mi][0], a[mi][1], a[mi][2], a[mi][3],
                      sA + row * 128 + (cb ^ ((row & 7) << 4)));
            }
            uint32_t b[4][2];
#pragma unroll
            for (int nb = 0; nb < 2; ++nb) {
                int row = warp_n * 32 + nb * 16 + la7 + b_rowsel;
                uint32_t cb = ks * 32 + b_cbsel;
                ldsm4(b[2 * nb][0], b[2 * nb][1], b[2 * nb + 1][0], b[2 * nb + 1][1],
                      sB + row * 128 + (cb ^ ((row & 7) << 4)));
            }
#pragma unroll
            for (int mi = 0; mi < 4; ++mi)
#pragma unroll
                for (int ni = 0; ni < 4; ++ni)
                    mma16816(c[mi][ni], a[mi], b[ni]);
        }
        __syncthreads();
    }

    // ---------------- epilogue ----------------
    int g = lane >> 2, tg = lane & 3;
#pragma unroll
    for (int mi = 0; mi < 4; ++mi) {
#pragma unroll
        for (int half = 0; half < 2; ++half) {
            int row = row0 + warp_m * 64 + mi * 16 + g + half * 8;
            const float* hsrow = (EPI == 0) ? (g_hs + (size_t)(row / LL) * II) : nullptr;
#pragma unroll
            for (int ni = 0; ni < 4; ++ni) {
                int col = col0 + warp_n * 32 + ni * 8 + tg * 2;
                float v0 = c[mi][ni][2 * half + 0];
                float v1 = c[mi][ni][2 * half + 1];
                v0 += bias[col];
                v1 += bias[col + 1];
                if (EPI == 0) {
                    v0 += hsrow[col];
                    v1 += hsrow[col + 1];
                    *(__half2*)(Ch + (size_t)row * N + col) = __floats2half2_rn(v0, v1);
                } else {
                    *(float2*)(Cf + (size_t)row * N + col) = make_float2(v0, v1);
                }
            }
        }
    }
}

// ---------------- softmax + z (L split 4-way per (b,d) pair) ----------------
// CTA = 256 threads handles 64 float2-lanes; 4 threads per lane (splits of
// 49 L-rows each). exp without max (|e| small). Two passes with smem combine.
__global__ __launch_bounds__(256)
void softmax_z_kernel(float* __restrict__ out) {
    __shared__ float2 sh[256];
    int t = threadIdx.x;
    int lanei = t & 63;              // lane within CTA
    int split = t >> 6;              // 0..3
    int pairi = blockIdx.x * 64 + lanei;
    int b = pairi / (DD / 2);
    int dp = pairi % (DD / 2);
    float2* e        = (float2*)(out + BB * DD + (size_t)b * LL * DD) + dp;
    const __half2* f = ((const __half2*)g_fv_h) + (size_t)b * LL * (DD / 2) + dp;
    const int str = DD / 2;
    int l0 = split * 49;

    float2 s = make_float2(0.f, 0.f);
    for (int l = l0; l < l0 + 49; ++l) {
        float2 v = e[(size_t)l * str];
        s.x += __expf(v.x);
        s.y += __expf(v.y);
    }
    sh[t] = s;
    __syncthreads();
    float sx = 0.f, sy = 0.f;
#pragma unroll
    for (int j = 0; j < 4; ++j) {
        float2 v = sh[lanei + 64 * j];
        sx += v.x;
        sy += v.y;
    }
    float2 inv = make_float2(1.f / sx, 1.f / sy);
    __syncthreads();

    float2 z = make_float2(0.f, 0.f);
    for (int l = l0; l < l0 + 49; ++l) {
        size_t off = (size_t)l * str;
        float2 v = e[off];
        float2 fw = __half22float2(f[off]);
        float2 p = make_float2(__expf(v.x) * inv.x, __expf(v.y) * inv.y);
        e[off] = p;
        z.x = fmaf(p.x, fw.x, z.x);
        z.y = fmaf(p.y, fw.y, z.y);
    }
    sh[t] = z;
    __syncthreads();
    if (split == 0) {
        float zx = z.x, zy = z.y;
#pragma unroll
        for (int j = 1; j < 4; ++j) {
            float2 v = sh[lanei + 64 * j];
            zx += v.x;
            zy += v.y;
        }
        ((float2*)out)[pairi] = make_float2(zx, zy);
    }
}

// ---------------- launch ----------------
#define GEMM_SMEM 65536

extern "C" void kernel_launch(void* const* d_in, const int* in_sizes, int n_in,
                              void* d_out, int out_size) {
    const float* fv     = (const float*)d_in[0];
    const float* hidden = (const float*)d_in[1];
    const float* Wf     = (const float*)d_in[2];
    const float* bf     = (const float*)d_in[3];
    const float* Wh     = (const float*)d_in[4];
    const float* bh     = (const float*)d_in[5];
    const float* Wa     = (const float*)d_in[6];
    const float* ba     = (const float*)d_in[7];
    float* out = (float*)d_out;

    cudaFuncSetAttribute(mma_gemm<0>, cudaFuncAttributeMaxDynamicSharedMemorySize, GEMM_SMEM);
    cudaFuncSetAttribute(mma_gemm<1>, cudaFuncAttributeMaxDynamicSharedMemorySize, GEMM_SMEM);

    void* p;
    cudaGetSymbolAddress(&p, g_fv_h);    f16* fv_h  = (f16*)p;
    cudaGetSymbolAddress(&p, g_fvs_h);   f16* fvs_h = (f16*)p;
    cudaGetSymbolAddress(&p, g_WfT_h);   f16* WfT_h = (f16*)p;
    cudaGetSymbolAddress(&p, g_WaT_h);   f16* WaT_h = (f16*)p;

    // all input conversions in one launch
    prep_kernel<<<PREP_BLOCKS, 256>>>(fv, hidden, Wh, bh, Wf, Wa);

    // gemm1: fvs = fv @ Wf + bf + hs   (M=12544, N=512, K0=2048) -> fp16
    mma_gemm<0><<<dim3(II / 128, MM / 128), 256, GEMM_SMEM>>>(
        fv_h, WfT_h, bf, nullptr, fvs_h, II, DD);

    // gemm2: e = fvs @ Wa + ba   (M=12544, N=2048, K0=512) -> fp32 into out
    float* e = out + BB * DD;
    mma_gemm<1><<<dim3(DD / 128, MM / 128), 256, GEMM_SMEM>>>(
        fvs_h, WaT_h, ba, e, nullptr, DD, II);

    // softmax over L (in place) + z
    softmax_z_kernel<<<BB * DD / 2 / 64, 256>>>(out);
}

// round 16
// speedup vs baseline: 1.2430x; 1.0437x over previous
#include <cuda_runtime.h>
#include <cuda_fp16.h>
#include <stdint.h>
#include <math.h>

#define BB 64
#define LL 196
#define DD 2048
#define II 512
#define MM (BB * LL)   // 12544

typedef __half f16;

// ---------------- device scratch (allocation-free) ----------------
__device__ f16 g_fv_h[(size_t)MM * DD];
__device__ f16 g_fvs_h[(size_t)MM * II];
__device__ f16 g_WfT_h[(size_t)II * DD];   // [I, D] K-major
__device__ f16 g_WaT_h[(size_t)DD * II];   // [D, I] K-major
__device__ float g_hs[BB * II];
__device__ int g_flag1[MM / 128];          // gemm1 row-block completion (memset/run)

// ---------------- helpers ----------------
__device__ __forceinline__ uint32_t smem_u32(const void* p) {
    uint32_t a;
    asm("{ .reg .u64 t; cvta.to.shared.u64 t, %1; cvt.u32.u64 %0, t; }"
        : "=r"(a) : "l"(p));
    return a;
}
__device__ __forceinline__ void cp_async16(uint32_t s, const void* g) {
    asm volatile("cp.async.cg.shared.global [%0], [%1], 16;" :: "r"(s), "l"(g));
}
__device__ __forceinline__ void cp_commit() {
    asm volatile("cp.async.commit_group;" ::: "memory");
}
__device__ __forceinline__ void cp_wait1() {
    asm volatile("cp.async.wait_group 1;" ::: "memory");
}
__device__ __forceinline__ void cp_wait0() {
    asm volatile("cp.async.wait_group 0;" ::: "memory");
}
__device__ __forceinline__ void ldsm4(uint32_t& r0, uint32_t& r1, uint32_t& r2,
                                      uint32_t& r3, uint32_t addr) {
    asm volatile("ldmatrix.sync.aligned.m8n8.x4.shared.b16 {%0,%1,%2,%3}, [%4];"
                 : "=r"(r0), "=r"(r1), "=r"(r2), "=r"(r3) : "r"(addr));
}
__device__ __forceinline__ void mma16816(float* c, const uint32_t* a,
                                         const uint32_t* b) {
    asm volatile(
        "mma.sync.aligned.m16n8k16.row.col.f32.f16.f16.f32 "
        "{%0,%1,%2,%3}, {%4,%5,%6,%7}, {%8,%9}, {%0,%1,%2,%3};"
        : "+f"(c[0]), "+f"(c[1]), "+f"(c[2]), "+f"(c[3])
        : "r"(a[0]), "r"(a[1]), "r"(a[2]), "r"(a[3]), "r"(b[0]), "r"(b[1]));
}

// ---------------- fused prep kernel ----------------
__device__ __forceinline__ void transpose_body(const float* __restrict__ in,
                                               f16* __restrict__ oh,
                                               int K, int N, int bx, int by,
                                               int tid, float (*t)[33]) {
    int n0 = bx * 32, k0 = by * 32;
    int tx = tid & 31, ty = tid >> 5;   // (32, 8)
#pragma unroll
    for (int i = 0; i < 32; i += 8)
        t[ty + i][tx] = in[(size_t)(k0 + ty + i) * N + n0 + tx];
    __syncthreads();
#pragma unroll
    for (int i = 0; i < 32; i += 8)
        oh[(size_t)(n0 + ty + i) * K + k0 + tx] = __float2half_rn(t[tx][ty + i]);
}

__global__ __launch_bounds__(256)
void prep_kernel(const float* __restrict__ fv, const float* __restrict__ hidden,
                 const float* __restrict__ Wh, const float* __restrict__ bh,
                 const float* __restrict__ Wf, const float* __restrict__ Wa) {
    __shared__ float t[32][33];
    int blk = blockIdx.x, tid = threadIdx.x;
    if (blk < 1024) {
        transpose_body(Wf, g_WfT_h, DD, II, blk & 15, blk >> 4, tid, t);
    } else if (blk < 2048) {
        int bb = blk - 1024;
        transpose_body(Wa, g_WaT_h, II, DD, bb & 63, bb >> 6, tid, t);
    } else if (blk < 2176) {
        int idx = (blk - 2048) * 256 + tid;   // 0..BB*II
        int b = idx >> 9, i = idx & 511;
        const float* h = hidden + b * II;
        float acc = bh[i];
#pragma unroll 4
        for (int j = 0; j < II; ++j)
            acc = fmaf(h[j], Wh[j * II + i], acc);
        g_hs[idx] = acc;
    } else {
        size_t i = (size_t)(blk - 2176) * 256 + tid;   // over MM*DD/4
        float4 v = ((const float4*)fv)[i];
        ((__half2*)g_fv_h)[2 * i]     = __floats2half2_rn(v.x, v.y);
        ((__half2*)g_fv_h)[2 * i + 1] = __floats2half2_rn(v.z, v.w);
    }
}
#define PREP_BLOCKS (2176 + (MM * DD / 4) / 256)

// ---------------- tensor-core (mma.sync) GEMM body ----------------
// C = A@B^T; A [M,K0] fp16 row-major, B [N,K0] fp16 K-major. Single pass.
// Tile 128x128, BK=64, 8 warps (64x32), 2-stage cp.async double buffer.
__device__ __forceinline__ void load_tile_async(uint32_t dst, const f16* src,
                                                int ldk, int tid) {
#pragma unroll
    for (int i = 0; i < 4; ++i) {
        int chunk = i * 256 + tid;
        int r = chunk >> 3, c16 = chunk & 7;
        const char* g = (const char*)src + (size_t)r * ldk * 2 + c16 * 16;
        uint32_t s = dst + r * 128 + ((c16 * 16) ^ ((r & 7) << 4));
        cp_async16(s, g);
    }
}

template <int EPI>
__device__ __forceinline__ void gemm_body(const f16* __restrict__ Ah,
                                          const f16* __restrict__ Bh,
                                          const float* __restrict__ bias,
                                          float* __restrict__ Cf,
                                          f16* __restrict__ Ch,
                                          int N, int K0, int row0, int col0,
                                          char* smem) {
    uint32_t sbase = smem_u32(smem);
    int tid = threadIdx.x, lane = tid & 31, wid = tid >> 5;
    int warp_m = wid >> 2, warp_n = wid & 3;

    float c[4][4][4];
#pragma unroll
    for (int mi = 0; mi < 4; ++mi)
#pragma unroll
        for (int ni = 0; ni < 4; ++ni)
#pragma unroll
            for (int f = 0; f < 4; ++f) c[mi][ni][f] = 0.f;

    int nch = K0 / 64;

    auto issue = [&](int cc) {
        int buf = cc & 1;
        int kk = cc * 64;
        load_tile_async(sbase + buf * 32768, Ah + (size_t)row0 * K0 + kk, K0, tid);
        load_tile_async(sbase + buf * 32768 + 16384, Bh + (size_t)col0 * K0 + kk, K0, tid);
        cp_commit();
    };

    issue(0);

    int la15 = lane & 15, la7 = lane & 7;
    int a_cbsel = (lane >> 4) * 16;
    int b_cbsel = ((lane >> 3) & 1) * 16;
    int b_rowsel = (lane >> 4) * 8;

    for (int cc = 0; cc < nch; ++cc) {
        if (cc + 1 < nch) { issue(cc + 1); cp_wait1(); }
        else              { cp_wait0(); }
        __syncthreads();

        uint32_t sA = sbase + (cc & 1) * 32768;
        uint32_t sB = sA + 16384;
#pragma unroll
        for (int ks = 0; ks < 4; ++ks) {
            uint32_t a[4][4];
#pragma unroll
            for (int mi = 0; mi < 4; ++mi) {
                int row = warp_m * 64 + mi * 16 + la15;
                uint32_t cb = ks * 32 + a_cbsel;
                ldsm4(a[mi][0], a[mi][1], a[mi][2], a[mi][3],
                      sA + row * 128 + (cb ^ ((row & 7) << 4)));
            }
            uint32_t b[4][2];
#pragma unroll
            for (int nb = 0; nb < 2; ++nb) {
                int row = warp_n * 32 + nb * 16 + la7 + b_rowsel;
                uint32_t cb = ks * 32 + b_cbsel;
                ldsm4(b[2 * nb][0], b[2 * nb][1], b[2 * nb + 1][0], b[2 * nb + 1][1],
                      sB + row * 128 + (cb ^ ((row & 7) << 4)));
            }
#pragma unroll
            for (int mi = 0; mi < 4; ++mi)
#pragma unroll
                for (int ni = 0; ni < 4; ++ni)
                    mma16816(c[mi][ni], a[mi], b[ni]);
        }
        __syncthreads();
    }

    int g = lane >> 2, tg = lane & 3;
#pragma unroll
    for (int mi = 0; mi < 4; ++mi) {
#pragma unroll
        for (int half = 0; half < 2; ++half) {
            int row = row0 + warp_m * 64 + mi * 16 + g + half * 8;
            const float* hsrow = (EPI == 0) ? (g_hs + (size_t)(row / LL) * II) : nullptr;
#pragma unroll
            for (int ni = 0; ni < 4; ++ni) {
                int col = col0 + warp_n * 32 + ni * 8 + tg * 2;
                float v0 = c[mi][ni][2 * half + 0];
                float v1 = c[mi][ni][2 * half + 1];
                v0 += bias[col];
                v1 += bias[col + 1];
                if (EPI == 0) {
                    v0 += hsrow[col];
                    v1 += hsrow[col + 1];
                    *(__half2*)(Ch + (size_t)row * N + col) = __floats2half2_rn(v0, v1);
                } else {
                    *(float2*)(Cf + (size_t)row * N + col) = make_float2(v0, v1);
                }
            }
        }
    }
}

// ---------------- fused gemm1 + gemm2 (one launch, flag-gated) ----------------
#define G1_CTAS ((II / 128) * (MM / 128))    // 392, mi-major
#define G2_CTAS ((DD / 128) * (MM / 128))    // 1568, mi-major

__global__ __launch_bounds__(256, 2)
void mma_fused(const f16* __restrict__ fv_h, const f16* __restrict__ WfT_h,
               const float* __restrict__ bf, f16* __restrict__ fvs_h,
               const f16* __restrict__ WaT_h, const float* __restrict__ ba,
               float* __restrict__ e) {
    extern __shared__ char smem[];
    int bid = blockIdx.x;
    if (bid < G1_CTAS) {
        int mi = bid >> 2, col = bid & 3;
        gemm_body<0>(fv_h, WfT_h, bf, nullptr, fvs_h, II, DD,
                     mi * 128, col * 128, smem);
        __threadfence();
        __syncthreads();
        if (threadIdx.x == 0) atomicAdd(&g_flag1[mi], 1);
    } else {
        int b2 = bid - G1_CTAS;
        int mi = b2 >> 4, col = b2 & 15;
        if (threadIdx.x == 0) {
            while (*(volatile int*)&g_flag1[mi] != 4) { }
        }
        __syncthreads();
        __threadfence();
        gemm_body<1>(fvs_h, WaT_h, ba, e, nullptr, DD, II,
                     mi * 128, col * 128, smem);
    }
}

// ---------------- softmax + z (L split 4-way per (b,d) pair) ----------------
__global__ __launch_bounds__(256)
void softmax_z_kernel(float* __restrict__ out) {
    __shared__ float2 sh[256];
    int t = threadIdx.x;
    int lanei = t & 63;
    int split = t >> 6;              // 0..3
    int pairi = blockIdx.x * 64 + lanei;
    int b = pairi / (DD / 2);
    int dp = pairi % (DD / 2);
    float2* e        = (float2*)(out + BB * DD + (size_t)b * LL * DD) + dp;
    const __half2* f = ((const __half2*)g_fv_h) + (size_t)b * LL * (DD / 2) + dp;
    const int str = DD / 2;
    int l0 = split * 49;

    float2 s = make_float2(0.f, 0.f);
    for (int l = l0; l < l0 + 49; ++l) {
        float2 v = e[(size_t)l * str];
        s.x += __expf(v.x);
        s.y += __expf(v.y);
    }
    sh[t] = s;
    __syncthreads();
    float sx = 0.f, sy = 0.f;
#pragma unroll
    for (int j = 0; j < 4; ++j) {
        float2 v = sh[lanei + 64 * j];
        sx += v.x;
        sy += v.y;
    }
    float2 inv = make_float2(1.f / sx, 1.f / sy);
    __syncthreads();

    float2 z = make_float2(0.f, 0.f);
    for (int l = l0; l < l0 + 49; ++l) {
        size_t off = (size_t)l * str;
        float2 v = e[off];
        float2 fw = __half22float2(f[off]);
        float2 p = make_float2(__expf(v.x) * inv.x, __expf(v.y) * inv.y);
        e[off] = p;
        z.x = fmaf(p.x, fw.x, z.x);
        z.y = fmaf(p.y, fw.y, z.y);
    }
    sh[t] = z;
    __syncthreads();
    if (split == 0) {
        float zx = z.x, zy = z.y;
#pragma unroll
        for (int j = 1; j < 4; ++j) {
            float2 v = sh[lanei + 64 * j];
            zx += v.x;
            zy += v.y;
        }
        ((float2*)out)[pairi] = make_float2(zx, zy);
    }
}

// ---------------- launch ----------------
#define GEMM_SMEM 65536

extern "C" void kernel_launch(void* const* d_in, const int* in_sizes, int n_in,
                              void* d_out, int out_size) {
    const float* fv     = (const float*)d_in[0];
    const float* hidden = (const float*)d_in[1];
    const float* Wf     = (const float*)d_in[2];
    const float* bf     = (const float*)d_in[3];
    const float* Wh     = (const float*)d_in[4];
    const float* bh     = (const float*)d_in[5];
    const float* Wa     = (const float*)d_in[6];
    const float* ba     = (const float*)d_in[7];
    float* out = (float*)d_out;

    cudaFuncSetAttribute(mma_fused, cudaFuncAttributeMaxDynamicSharedMemorySize, GEMM_SMEM);

    void* p;
    cudaGetSymbolAddress(&p, g_fv_h);    f16* fv_h  = (f16*)p;
    cudaGetSymbolAddress(&p, g_fvs_h);   f16* fvs_h = (f16*)p;
    cudaGetSymbolAddress(&p, g_WfT_h);   f16* WfT_h = (f16*)p;
    cudaGetSymbolAddress(&p, g_WaT_h);   f16* WaT_h = (f16*)p;
    void* flag_ptr; cudaGetSymbolAddress(&flag_ptr, g_flag1);

    // reset flags + all input conversions
    cudaMemsetAsync(flag_ptr, 0, sizeof(int) * (MM / 128));
    prep_kernel<<<PREP_BLOCKS, 256>>>(fv, hidden, Wh, bh, Wf, Wa);

    // fused gemm1 (producer) + gemm2 (consumer) in one launch
    float* e = out + BB * DD;
    mma_fused<<<G1_CTAS + G2_CTAS, 256, GEMM_SMEM>>>(
        fv_h, WfT_h, bf, fvs_h, WaT_h, ba, e);

    // softmax over L (in place) + z
    softmax_z_kernel<<<BB * DD / 2 / 64, 256>>>(out);
}

// round 17
// speedup vs baseline: 1.3760x; 1.1070x over previous
#include <cuda_runtime.h>
#include <cuda_fp16.h>
#include <stdint.h>
#include <math.h>

#define BB 64
#define LL 196
#define DD 2048
#define II 512
#define MM (BB * LL)   // 12544

typedef __half f16;

// ---------------- device scratch (allocation-free) ----------------
__device__ f16 g_fv_h[(size_t)MM * DD];
__device__ f16 g_fvs_h[(size_t)MM * II];
__device__ f16 g_WfT_h[(size_t)II * DD];   // [I, D] K-major
__device__ f16 g_WaT_h[(size_t)DD * II];   // [D, I] K-major
__device__ float g_hs[BB * II];
__device__ int g_flag1[MM / 128];          // gemm1 row-block completion (memset/run)

// ---------------- helpers ----------------
__device__ __forceinline__ uint32_t smem_u32(const void* p) {
    uint32_t a;
    asm("{ .reg .u64 t; cvta.to.shared.u64 t, %1; cvt.u32.u64 %0, t; }"
        : "=r"(a) : "l"(p));
    return a;
}
__device__ __forceinline__ void cp_async16(uint32_t s, const void* g) {
    asm volatile("cp.async.cg.shared.global [%0], [%1], 16;" :: "r"(s), "l"(g));
}
__device__ __forceinline__ void cp_commit() {
    asm volatile("cp.async.commit_group;" ::: "memory");
}
__device__ __forceinline__ void cp_wait1() {
    asm volatile("cp.async.wait_group 1;" ::: "memory");
}
__device__ __forceinline__ void cp_wait0() {
    asm volatile("cp.async.wait_group 0;" ::: "memory");
}
__device__ __forceinline__ void ldsm4(uint32_t& r0, uint32_t& r1, uint32_t& r2,
                                      uint32_t& r3, uint32_t addr) {
    asm volatile("ldmatrix.sync.aligned.m8n8.x4.shared.b16 {%0,%1,%2,%3}, [%4];"
                 : "=r"(r0), "=r"(r1), "=r"(r2), "=r"(r3) : "r"(addr));
}
__device__ __forceinline__ void mma16816(float* c, const uint32_t* a,
                                         const uint32_t* b) {
    asm volatile(
        "mma.sync.aligned.m16n8k16.row.col.f32.f16.f16.f32 "
        "{%0,%1,%2,%3}, {%4,%5,%6,%7}, {%8,%9}, {%0,%1,%2,%3};"
        : "+f"(c[0]), "+f"(c[1]), "+f"(c[2]), "+f"(c[3])
        : "r"(a[0]), "r"(a[1]), "r"(a[2]), "r"(a[3]), "r"(b[0]), "r"(b[1]));
}

// ---------------- fused prep kernel ----------------
// blocks [0,1024): transpose Wf; [1024,2048): transpose Wa;
// [2048,2176): hs (MLP-optimized); [2176,...): fv->fp16, 4 float4/thread.
__device__ __forceinline__ void transpose_body(const float* __restrict__ in,
                                               f16* __restrict__ oh,
                                               int K, int N, int bx, int by,
                                               int tid, float (*t)[33]) {
    int n0 = bx * 32, k0 = by * 32;
    int tx = tid & 31, ty = tid >> 5;   // (32, 8)
#pragma unroll
    for (int i = 0; i < 32; i += 8)
        t[ty + i][tx] = in[(size_t)(k0 + ty + i) * N + n0 + tx];
    __syncthreads();
#pragma unroll
    for (int i = 0; i < 32; i += 8)
        oh[(size_t)(n0 + ty + i) * K + k0 + tx] = __float2half_rn(t[tx][ty + i]);
}

__global__ __launch_bounds__(256)
void prep_kernel(const float* __restrict__ fv, const float* __restrict__ hidden,
                 const float* __restrict__ Wh, const float* __restrict__ bh,
                 const float* __restrict__ Wf, const float* __restrict__ Wa) {
    __shared__ float t[32][33];
    int blk = blockIdx.x, tid = threadIdx.x;
    if (blk < 1024) {
        transpose_body(Wf, g_WfT_h, DD, II, blk & 15, blk >> 4, tid, t);
    } else if (blk < 2048) {
        int bb = blk - 1024;
        transpose_body(Wa, g_WaT_h, II, DD, bb & 63, bb >> 6, tid, t);
    } else if (blk < 2176) {
        int idx = (blk - 2048) * 256 + tid;   // 0..BB*II
        int b = idx >> 9, i = idx & 511;
        const float* h = hidden + b * II;
        const float* w = Wh + i;
        float a0 = bh[i], a1 = 0.f, a2 = 0.f, a3 = 0.f;
#pragma unroll 2
        for (int j = 0; j < II; j += 4) {
            a0 = fmaf(h[j],     w[(size_t)j * II],       a0);
            a1 = fmaf(h[j + 1], w[(size_t)(j + 1) * II], a1);
            a2 = fmaf(h[j + 2], w[(size_t)(j + 2) * II], a2);
            a3 = fmaf(h[j + 3], w[(size_t)(j + 3) * II], a3);
        }
        g_hs[idx] = (a0 + a1) + (a2 + a3);
    } else {
        // 4 independent float4 chunks per thread (MLP=4)
        size_t base = (size_t)(blk - 2176) * 1024 + tid;
        float4 v[4];
#pragma unroll
        for (int j = 0; j < 4; ++j) v[j] = ((const float4*)fv)[base + 256 * j];
#pragma unroll
        for (int j = 0; j < 4; ++j) {
            size_t o = base + 256 * j;
            ((__half2*)g_fv_h)[2 * o]     = __floats2half2_rn(v[j].x, v[j].y);
            ((__half2*)g_fv_h)[2 * o + 1] = __floats2half2_rn(v[j].z, v[j].w);
        }
    }
}
#define PREP_BLOCKS (2176 + (MM * DD / 4) / 1024)

// ---------------- tensor-core (mma.sync) GEMM body ----------------
__device__ __forceinline__ void load_tile_async(uint32_t dst, const f16* src,
                                                int ldk, int tid) {
#pragma unroll
    for (int i = 0; i < 4; ++i) {
        int chunk = i * 256 + tid;
        int r = chunk >> 3, c16 = chunk & 7;
        const char* g = (const char*)src + (size_t)r * ldk * 2 + c16 * 16;
        uint32_t s = dst + r * 128 + ((c16 * 16) ^ ((r & 7) << 4));
        cp_async16(s, g);
    }
}

template <int EPI>
__device__ __forceinline__ void gemm_body(const f16* __restrict__ Ah,
                                          const f16* __restrict__ Bh,
                                          const float* __restrict__ bias,
                                          float* __restrict__ Cf,
                                          f16* __restrict__ Ch,
                                          int N, int K0, int row0, int col0,
                                          char* smem) {
    uint32_t sbase = smem_u32(smem);
    int tid = threadIdx.x, lane = tid & 31, wid = tid >> 5;
    int warp_m = wid >> 2, warp_n = wid & 3;

    float c[4][4][4];
#pragma unroll
    for (int mi = 0; mi < 4; ++mi)
#pragma unroll
        for (int ni = 0; ni < 4; ++ni)
#pragma unroll
            for (int f = 0; f < 4; ++f) c[mi][ni][f] = 0.f;

    int nch = K0 / 64;

    auto issue = [&](int cc) {
        int buf = cc & 1;
        int kk = cc * 64;
        load_tile_async(sbase + buf * 32768, Ah + (size_t)row0 * K0 + kk, K0, tid);
        load_tile_async(sbase + buf * 32768 + 16384, Bh + (size_t)col0 * K0 + kk, K0, tid);
        cp_commit();
    };

    issue(0);

    int la15 = lane & 15, la7 = lane & 7;
    int a_cbsel = (lane >> 4) * 16;
    int b_cbsel = ((lane >> 3) & 1) * 16;
    int b_rowsel = (lane >> 4) * 8;

    for (int cc = 0; cc < nch; ++cc) {
        if (cc + 1 < nch) { issue(cc + 1); cp_wait1(); }
        else              { cp_wait0(); }
        __syncthreads();

        uint32_t sA = sbase + (cc & 1) * 32768;
        uint32_t sB = sA + 16384;
#pragma unroll
        for (int ks = 0; ks < 4; ++ks) {
            uint32_t a[4][4];
#pragma unroll
            for (int mi = 0; mi < 4; ++mi) {
                int row = warp_m * 64 + mi * 16 + la15;
                uint32_t cb = ks * 32 + a_cbsel;
                ldsm4(a[mi][0], a[mi][1], a[mi][2], a[mi][3],
                      sA + row * 128 + (cb ^ ((row & 7) << 4)));
            }
            uint32_t b[4][2];
#pragma unroll
            for (int nb = 0; nb < 2; ++nb) {
                int row = warp_n * 32 + nb * 16 + la7 + b_rowsel;
                uint32_t cb = ks * 32 + b_cbsel;
                ldsm4(b[2 * nb][0], b[2 * nb][1], b[2 * nb + 1][0], b[2 * nb + 1][1],
                      sB + row * 128 + (cb ^ ((row & 7) << 4)));
            }
#pragma unroll
            for (int mi = 0; mi < 4; ++mi)
#pragma unroll
                for (int ni = 0; ni < 4; ++ni)
                    mma16816(c[mi][ni], a[mi], b[ni]);
        }
        __syncthreads();
    }

    int g = lane >> 2, tg = lane & 3;
#pragma unroll
    for (int mi = 0; mi < 4; ++mi) {
#pragma unroll
        for (int half = 0; half < 2; ++half) {
            int row = row0 + warp_m * 64 + mi * 16 + g + half * 8;
            const float* hsrow = (EPI == 0) ? (g_hs + (size_t)(row / LL) * II) : nullptr;
#pragma unroll
            for (int ni = 0; ni < 4; ++ni) {
                int col = col0 + warp_n * 32 + ni * 8 + tg * 2;
                float v0 = c[mi][ni][2 * half + 0];
                float v1 = c[mi][ni][2 * half + 1];
                v0 += bias[col];
                v1 += bias[col + 1];
                if (EPI == 0) {
                    v0 += hsrow[col];
                    v1 += hsrow[col + 1];
                    *(__half2*)(Ch + (size_t)row * N + col) = __floats2half2_rn(v0, v1);
                } else {
                    *(float2*)(Cf + (size_t)row * N + col) = make_float2(v0, v1);
                }
            }
        }
    }
}

// ---------------- fused gemm1 + gemm2 (one launch, flag-gated) ----------------
#define G1_CTAS ((II / 128) * (MM / 128))    // 392, mi-major
#define G2_CTAS ((DD / 128) * (MM / 128))    // 1568, mi-major

__global__ __launch_bounds__(256, 2)
void mma_fused(const f16* __restrict__ fv_h, const f16* __restrict__ WfT_h,
               const float* __restrict__ bf, f16* __restrict__ fvs_h,
               const f16* __restrict__ WaT_h, const float* __restrict__ ba,
               float* __restrict__ e) {
    extern __shared__ char smem[];
    int bid = blockIdx.x;
    if (bid < G1_CTAS) {
        int mi = bid >> 2, col = bid & 3;
        gemm_body<0>(fv_h, WfT_h, bf, nullptr, fvs_h, II, DD,
                     mi * 128, col * 128, smem);
        __threadfence();
        __syncthreads();
        if (threadIdx.x == 0) atomicAdd(&g_flag1[mi], 1);
    } else {
        int b2 = bid - G1_CTAS;
        int mi = b2 >> 4, col = b2 & 15;
        if (threadIdx.x == 0) {
            while (*(volatile int*)&g_flag1[mi] != 4) { }
        }
        __syncthreads();
        __threadfence();
        gemm_body<1>(fvs_h, WaT_h, ba, e, nullptr, DD, II,
                     mi * 128, col * 128, smem);
    }
}

// ---------------- softmax + z (L split 4-way per (b,d) pair) ----------------
__global__ __launch_bounds__(256)
void softmax_z_kernel(float* __restrict__ out) {
    __shared__ float2 sh[256];
    int t = threadIdx.x;
    int lanei = t & 63;
    int split = t >> 6;              // 0..3
    int pairi = blockIdx.x * 64 + lanei;
    int b = pairi / (DD / 2);
    int dp = pairi % (DD / 2);
    float2* e        = (float2*)(out + BB * DD + (size_t)b * LL * DD) + dp;
    const __half2* f = ((const __half2*)g_fv_h) + (size_t)b * LL * (DD / 2) + dp;
    const int str = DD / 2;
    int l0 = split * 49;

    float2 s = make_float2(0.f, 0.f);
    for (int l = l0; l < l0 + 49; ++l) {
        float2 v = e[(size_t)l * str];
        s.x += __expf(v.x);
        s.y += __expf(v.y);
    }
    sh[t] = s;
    __syncthreads();
    float sx = 0.f, sy = 0.f;
#pragma unroll
    for (int j = 0; j < 4; ++j) {
        float2 v = sh[lanei + 64 * j];
        sx += v.x;
        sy += v.y;
    }
    float2 inv = make_float2(1.f / sx, 1.f / sy);
    __syncthreads();

    float2 z = make_float2(0.f, 0.f);
    for (int l = l0; l < l0 + 49; ++l) {
        size_t off = (size_t)l * str;
        float2 v = e[off];
        float2 fw = __half22float2(f[off]);
        float2 p = make_float2(__expf(v.x) * inv.x, __expf(v.y) * inv.y);
        e[off] = p;
        z.x = fmaf(p.x, fw.x, z.x);
        z.y = fmaf(p.y, fw.y, z.y);
    }
    sh[t] = z;
    __syncthreads();
    if (split == 0) {
        float zx = z.x, zy = z.y;
#pragma unroll
        for (int j = 1; j < 4; ++j) {
            float2 v = sh[lanei + 64 * j];
            zx += v.x;
            zy += v.y;
        }
        ((float2*)out)[pairi] = make_float2(zx, zy);
    }
}

// ---------------- launch ----------------
#define GEMM_SMEM 65536

extern "C" void kernel_launch(void* const* d_in, const int* in_sizes, int n_in,
                              void* d_out, int out_size) {
    const float* fv     = (const float*)d_in[0];
    const float* hidden = (const float*)d_in[1];
    const float* Wf     = (const float*)d_in[2];
    const float* bf     = (const float*)d_in[3];
    const float* Wh     = (const float*)d_in[4];
    const float* bh     = (const float*)d_in[5];
    const float* Wa     = (const float*)d_in[6];
    const float* ba     = (const float*)d_in[7];
    float* out = (float*)d_out;

    cudaFuncSetAttribute(mma_fused, cudaFuncAttributeMaxDynamicSharedMemorySize, GEMM_SMEM);

    void* p;
    cudaGetSymbolAddress(&p, g_fv_h);    f16* fv_h  = (f16*)p;
    cudaGetSymbolAddress(&p, g_fvs_h);   f16* fvs_h = (f16*)p;
    cudaGetSymbolAddress(&p, g_WfT_h);   f16* WfT_h = (f16*)p;
    cudaGetSymbolAddress(&p, g_WaT_h);   f16* WaT_h = (f16*)p;
    void* flag_ptr; cudaGetSymbolAddress(&flag_ptr, g_flag1);

    // reset flags + all input conversions
    cudaMemsetAsync(flag_ptr, 0, sizeof(int) * (MM / 128));
    prep_kernel<<<PREP_BLOCKS, 256>>>(fv, hidden, Wh, bh, Wf, Wa);

    // fused gemm1 (producer) + gemm2 (consumer) in one launch
    float* e = out + BB * DD;
    mma_fused<<<G1_CTAS + G2_CTAS, 256, GEMM_SMEM>>>(
        fv_h, WfT_h, bf, fvs_h, WaT_h, ba, e);

    // softmax over L (in place) + z
    softmax_z_kernel<<<BB * DD / 2 / 64, 256>>>(out);
}